// round 13
// baseline (speedup 1.0000x reference)
#include <cuda_runtime.h>
#include <cuda_fp16.h>
#include <cstdint>
#include <math.h>

// Problem constants
#define D_MODEL 1024
#define NHEADS  16
#define DK      64
#define BATCH   2048
#define SEQ     20
#define M_TOTAL (BATCH * SEQ)   // 40960

// ---------------------------------------------------------------------------
// Scratch (fp16): W conversions + q/k/v. X is now read fp32 by the GEMM.
// ---------------------------------------------------------------------------
__device__ __half g_wh[3][(size_t)D_MODEL * D_MODEL];
__device__ __half g_qh[(size_t)M_TOTAL * D_MODEL];
__device__ __half g_kh[(size_t)M_TOTAL * D_MODEL];
__device__ __half g_vh[(size_t)M_TOTAL * D_MODEL];

struct alignas(16) Half8 { __half2 a, b, c, d; };

// ---------------------------------------------------------------------------
// W-only fp32 -> fp16 conversion (streaming). 256 blocks per W.
// ---------------------------------------------------------------------------
#define WBLKS 256

__global__ __launch_bounds__(256) void f2h_w(
    const float* __restrict__ Wq, const float* __restrict__ Wk, const float* __restrict__ Wv)
{
    int w = blockIdx.x / WBLKS;
    int local = blockIdx.x % WBLKS;
    const float* src = (w == 0) ? Wq : (w == 1) ? Wk : Wv;
    __half* dst = &g_wh[w][0];

    int c0 = (local * 256 + threadIdx.x) * 2;    // Half8 chunks, exact fit
    float4 v[4];
    #pragma unroll
    for (int u = 0; u < 4; u++)
        v[u] = __ldcs(&((const float4*)src)[c0 * 2 + u]);
    #pragma unroll
    for (int u = 0; u < 2; u++) {
        Half8 h;
        h.a = __floats2half2_rn(v[2 * u].x,     v[2 * u].y);
        h.b = __floats2half2_rn(v[2 * u].z,     v[2 * u].w);
        h.c = __floats2half2_rn(v[2 * u + 1].x, v[2 * u + 1].y);
        h.d = __floats2half2_rn(v[2 * u + 1].z, v[2 * u + 1].w);
        __stcs((float4*)&((Half8*)dst)[c0 + u], *(float4*)&h);
    }
}

// ---------------------------------------------------------------------------
// MMA / ldmatrix helpers
// ---------------------------------------------------------------------------
__device__ __forceinline__ void mma16(float* c, const uint32_t* a, const uint32_t* b) {
    asm volatile(
        "mma.sync.aligned.m16n8k16.row.col.f32.f16.f16.f32 "
        "{%0,%1,%2,%3}, {%4,%5,%6,%7}, {%8,%9}, {%0,%1,%2,%3};"
        : "+f"(c[0]), "+f"(c[1]), "+f"(c[2]), "+f"(c[3])
        : "r"(a[0]), "r"(a[1]), "r"(a[2]), "r"(a[3]),
          "r"(b[0]), "r"(b[1]));
}

__device__ __forceinline__ void ldmatrix_x4(uint32_t* r, uint32_t addr) {
    asm volatile("ldmatrix.sync.aligned.m8n8.x4.shared.b16 {%0,%1,%2,%3}, [%4];"
                 : "=r"(r[0]), "=r"(r[1]), "=r"(r[2]), "=r"(r[3]) : "r"(addr));
}
__device__ __forceinline__ void ldmatrix_x2(uint32_t* r, uint32_t addr) {
    asm volatile("ldmatrix.sync.aligned.m8n8.x2.shared.b16 {%0,%1}, [%2];"
                 : "=r"(r[0]), "=r"(r[1]) : "r"(addr));
}

__device__ __forceinline__ void cp16(uint32_t saddr, const void* g) {
    asm volatile("cp.async.cg.shared.global [%0], [%1], 16;\n" :: "r"(saddr), "l"(g));
}
#define CP_COMMIT() asm volatile("cp.async.commit_group;\n" ::: "memory")
#define CP_WAIT(n)  asm volatile("cp.async.wait_group %0;\n" :: "n"(n) : "memory")

__device__ __forceinline__ uint32_t smem_u32(const void* p) {
    uint32_t a;
    asm("{ .reg .u64 t; cvta.to.shared.u64 t, %1; cvt.u32.u64 %0, t; }"
        : "=r"(a) : "l"(p));
    return a;
}

__device__ __forceinline__ uint32_t packh2(float2 f) {
    __half2 h = __floats2half2_rn(f.x, f.y);
    return *(uint32_t*)&h;
}

// ---------------------------------------------------------------------------
// Projection GEMM: Y = X(fp32) @ W(fp16)^T + b, fp16 output. 2 CTAs/SM.
// BM=128, BN=128, BK=32, 3-stage cp.async.
// A stage: fp32, row stride 40 floats. Fragment loads are float2 (LDS.64):
//   lane (g,tq) reads banks (8g + 2tq, +1) -> each 16-lane phase covers all
//   32 banks exactly once: conflict-free. Converted to fp16 at frag build.
// B stage: fp16, row stride 20 words (validated conflict-free pattern).
// ---------------------------------------------------------------------------
#define GM_BM 128
#define GM_BN 128
#define GM_BK 32
#define ASTRIDE 40                         // floats per A row
#define BSTRIDE 20                         // words per B row
#define A_STG_WORDS (GM_BM * ASTRIDE)      // 5120
#define B_STG_WORDS (GM_BN * BSTRIDE)      // 2560
#define STG_WORDS   (A_STG_WORDS + B_STG_WORDS)  // 7680
#define NSTAGE 3
#define GM_SMEM_BYTES (NSTAGE * STG_WORDS * 4)   // 92160 (2 CTAs = 184320)
#define GM_KT (D_MODEL / GM_BK)            // 32

__global__ __launch_bounds__(256, 2) void proj_gemm(
    const float* __restrict__ X,
    const float* __restrict__ bq, const float* __restrict__ bk, const float* __restrict__ bv)
{
    extern __shared__ uint32_t smem[];
    const uint32_t sb = smem_u32(smem);

    const int tid  = threadIdx.x;
    const int lane = tid & 31;
    const int warp = tid >> 5;
    const int wr   = warp >> 2;
    const int wc   = warp & 3;
    const int g    = lane >> 2;
    const int tq   = lane & 3;

    const int proj  = blockIdx.x >> 3;
    const int nBase = (blockIdx.x & 7) * GM_BN;
    const int mBase = blockIdx.y * GM_BM;

    const __half* Wp = g_wh[proj];

    auto load_stage = [&](int stg, int kt) {
        uint32_t base = sb + stg * (STG_WORDS * 4);
        int k0 = kt * GM_BK;
        // A: 128 rows x 8 chunks (16B = 4 floats) = 1024
        #pragma unroll
        for (int i = 0; i < 4; i++) {
            int ch = tid + i * 256;
            int r = ch >> 3, c = ch & 7;
            cp16(base + (r * ASTRIDE + c * 4) * 4,
                 &X[(size_t)(mBase + r) * D_MODEL + k0 + c * 4]);
        }
        // B: 128 rows x 4 chunks (16B = 8 halves) = 512
        #pragma unroll
        for (int i = 0; i < 2; i++) {
            int ch = tid + i * 256;
            int r = ch >> 2, c = ch & 3;
            cp16(base + (A_STG_WORDS + r * BSTRIDE + c * 4) * 4,
                 &Wp[(size_t)(nBase + r) * D_MODEL + k0 + c * 8]);
        }
        CP_COMMIT();
    };

    float c[4][4][4];
    #pragma unroll
    for (int mt = 0; mt < 4; mt++)
        #pragma unroll
        for (int nt = 0; nt < 4; nt++)
            #pragma unroll
            for (int i = 0; i < 4; i++) c[mt][nt][i] = 0.f;

    load_stage(0, 0);
    load_stage(1, 1);

    for (int kt = 0; kt < GM_KT; kt++) {
        int stg = kt % NSTAGE;
        if (kt + 2 < GM_KT) load_stage((kt + 2) % NSTAGE, kt + 2);
        if (kt < GM_KT - 2)      CP_WAIT(2);
        else if (kt == GM_KT - 2) CP_WAIT(1);
        else                      CP_WAIT(0);
        __syncthreads();

        const float*    sAf = (const float*)(smem + stg * STG_WORDS);
        const uint32_t* sBw = smem + stg * STG_WORDS + A_STG_WORDS;

        #pragma unroll
        for (int ks = 0; ks < 2; ks++) {
            uint32_t af[4][4], bf[4][2];
            #pragma unroll
            for (int mt = 0; mt < 4; mt++) {
                const float* ab = sAf + (wr * 64 + mt * 16 + g) * ASTRIDE
                                + ks * 16 + 2 * tq;
                af[mt][0] = packh2(*(const float2*)(ab));
                af[mt][1] = packh2(*(const float2*)(ab + 8 * ASTRIDE));
                af[mt][2] = packh2(*(const float2*)(ab + 8));
                af[mt][3] = packh2(*(const float2*)(ab + 8 * ASTRIDE + 8));
            }
            const int kw = ks * 8 + tq;
            #pragma unroll
            for (int nt = 0; nt < 4; nt++) {
                int rb = (wc * 32 + nt * 8 + g) * BSTRIDE + kw;
                bf[nt][0] = sBw[rb];
                bf[nt][1] = sBw[rb + 4];
            }
            #pragma unroll
            for (int mt = 0; mt < 4; mt++)
                #pragma unroll
                for (int nt = 0; nt < 4; nt++)
                    mma16(c[mt][nt], af[mt], bf[nt]);
        }
        __syncthreads();
    }

    const float* bp = (proj == 0) ? bq : (proj == 1) ? bk : bv;
    __half* outp    = (proj == 0) ? g_qh : (proj == 1) ? g_kh : g_vh;
    #pragma unroll
    for (int mt = 0; mt < 4; mt++) {
        #pragma unroll
        for (int nt = 0; nt < 4; nt++) {
            int row = mBase + wr * 64 + mt * 16 + g;
            int col = nBase + wc * 32 + nt * 8 + 2 * tq;
            float b0 = bp[col], b1 = bp[col + 1];
            __half2 h01 = __floats2half2_rn(c[mt][nt][0] + b0, c[mt][nt][1] + b1);
            __half2 h23 = __floats2half2_rn(c[mt][nt][2] + b0, c[mt][nt][3] + b1);
            *(__half2*)&outp[(size_t)row * D_MODEL + col] = h01;
            *(__half2*)&outp[(size_t)(row + 8) * D_MODEL + col] = h23;
        }
    }
}

// ---------------------------------------------------------------------------
// Attention + decay (R9/R12-validated). Score phase on tensor cores;
// reversed block order (L2-warm q/k/v first); streaming output stores.
// ---------------------------------------------------------------------------
#define QK_STRIDE 72   // halves per row; 144 B = 9 x 16 B (ldmatrix-aligned)

__global__ __launch_bounds__(128) void attn_kernel(
    const int* __restrict__ lenbuf, float* __restrict__ out)
{
    const int bh = (BATCH * NHEADS - 1) - blockIdx.x;   // reversed order
    const int b  = bh >> 4;
    const int h  = bh & 15;
    const int tid  = threadIdx.x;
    const int warp = tid >> 5;
    const int lane = tid & 31;

    __shared__ __align__(16) __half sqh[32][QK_STRIDE];
    __shared__ __align__(16) __half skh[24][QK_STRIDE];
    __shared__ __align__(16) float sv[SEQ][68];
    __shared__ float ssc[SEQ][24];
    __shared__ float sinv[SEQ];
    __shared__ __align__(16) float wgtT[SEQ][24];   // [j][i]

    for (int i = tid; i < 32 * (QK_STRIDE / 2); i += 128) ((uint32_t*)sqh)[i] = 0;
    for (int i = tid; i < 24 * (QK_STRIDE / 2); i += 128) ((uint32_t*)skh)[i] = 0;
    __syncthreads();

    {
        size_t base = (size_t)(b * SEQ) * D_MODEL + h * DK;
        for (int e = tid; e < SEQ * (DK / 8); e += 128) {
            int s = e >> 3, d8 = (e & 7) * 8;
            size_t gi = base + (size_t)s * D_MODEL + d8;
            Half8 q8 = *(const Half8*)&g_qh[gi];
            Half8 k8 = *(const Half8*)&g_kh[gi];
            Half8 v8 = *(const Half8*)&g_vh[gi];
            *(Half8*)&sqh[s][d8] = q8;
            *(Half8*)&skh[s][d8] = k8;
            float2 fa = __half22float2(v8.a), fb = __half22float2(v8.b);
            float2 fc = __half22float2(v8.c), fd = __half22float2(v8.d);
            *(float4*)&sv[s][d8]     = make_float4(fa.x, fa.y, fb.x, fb.y);
            *(float4*)&sv[s][d8 + 4] = make_float4(fc.x, fc.y, fd.x, fd.y);
        }
    }
    __syncthreads();

    // length may be int64 or int32 (jax x64 config). All lengths >= 1,
    // so int32-view word 1 == 0 iff buffer is int64.
    bool is64 = (lenbuf[1] == 0);
    int len = is64 ? lenbuf[2 * b] : lenbuf[b];

    if (warp < 3) {
        float c[2][4];
        #pragma unroll
        for (int mt = 0; mt < 2; mt++)
            #pragma unroll
            for (int i = 0; i < 4; i++) c[mt][i] = 0.f;

        const uint32_t sq_base = smem_u32(&sqh[0][0]);
        const uint32_t sk_base = smem_u32(&skh[0][0]);

        #pragma unroll
        for (int ks = 0; ks < 4; ks++) {
            uint32_t bfrag[2];
            {
                int l = lane & 15;
                int row = warp * 8 + (l & 7);
                int col = ks * 16 + ((l >> 3) & 1) * 8;
                ldmatrix_x2(bfrag, sk_base + (row * QK_STRIDE + col) * 2);
            }
            #pragma unroll
            for (int mt = 0; mt < 2; mt++) {
                uint32_t afrag[4];
                int row = mt * 16 + (lane & 15);
                int col = ks * 16 + (lane >> 4) * 8;
                ldmatrix_x4(afrag, sq_base + (row * QK_STRIDE + col) * 2);
                mma16(c[mt], afrag, bfrag);
            }
        }

        int jc = warp * 8 + 2 * (lane & 3);
        bool jv0 = (jc < SEQ), jv1 = (jc + 1 < SEQ);
        float m0 = (jc < len) ? 1.f : 0.f;
        float m1 = (jc + 1 < len) ? 1.f : 0.f;
        #pragma unroll
        for (int mt = 0; mt < 2; mt++) {
            #pragma unroll
            for (int hrow = 0; hrow < 2; hrow++) {
                int r = mt * 16 + (lane >> 2) + hrow * 8;
                if (r < SEQ) {
                    if (jv0) ssc[r][jc]     = m0 * __expf(c[mt][2 * hrow]     * 0.125f);
                    if (jv1) ssc[r][jc + 1] = m1 * __expf(c[mt][2 * hrow + 1] * 0.125f);
                }
            }
        }
    }
    __syncthreads();

    if (tid < SEQ) {
        float s = 0.f;
        #pragma unroll
        for (int j = 0; j < SEQ; j++) s += ssc[tid][j];
        sinv[tid] = 1.f / (s + 1e-8f);
    }
    __syncthreads();

    for (int e = tid; e < SEQ * SEQ; e += 128) {
        int i = e % SEQ, j = e / SEQ;
        wgtT[j][i] = ssc[i][j] * sinv[i] - (float)((i > j) ? (i - j) : (j - i));
    }
    __syncthreads();

    if (tid < 80) {
        int i0 = (tid / 16) * 4;
        int d0 = (tid & 15) * 4;
        float4 o0 = {0, 0, 0, 0}, o1 = {0, 0, 0, 0}, o2 = {0, 0, 0, 0}, o3 = {0, 0, 0, 0};
        #pragma unroll
        for (int j = 0; j < SEQ; j++) {
            float4 vv = *(const float4*)&sv[j][d0];
            float4 w  = *(const float4*)&wgtT[j][i0];
            o0.x += w.x * vv.x; o0.y += w.x * vv.y; o0.z += w.x * vv.z; o0.w += w.x * vv.w;
            o1.x += w.y * vv.x; o1.y += w.y * vv.y; o1.z += w.y * vv.z; o1.w += w.y * vv.w;
            o2.x += w.z * vv.x; o2.y += w.z * vv.y; o2.z += w.z * vv.z; o2.w += w.z * vv.w;
            o3.x += w.w * vv.x; o3.y += w.w * vv.y; o3.z += w.w * vv.z; o3.w += w.w * vv.w;
        }
        size_t base = (size_t)(b * SEQ + i0) * D_MODEL + h * DK + d0;
        __stcs((float4*)&out[base],               o0);
        __stcs((float4*)&out[base + D_MODEL],     o1);
        __stcs((float4*)&out[base + 2 * D_MODEL], o2);
        __stcs((float4*)&out[base + 3 * D_MODEL], o3);
    }
}

// ---------------------------------------------------------------------------
// Inputs (metadata order): Q, W_Q, b_Q, W_K, b_K, W_V, b_V, length
// ---------------------------------------------------------------------------
extern "C" void kernel_launch(void* const* d_in, const int* in_sizes, int n_in,
                              void* d_out, int out_size)
{
    const float* X  = (const float*)d_in[0];
    const float* Wq = (const float*)d_in[1];
    const float* bq = (const float*)d_in[2];
    const float* Wk = (const float*)d_in[3];
    const float* bk = (const float*)d_in[4];
    const float* Wv = (const float*)d_in[5];
    const float* bv = (const float*)d_in[6];
    const int*   ln = (const int*)d_in[7];

    f2h_w<<<3 * WBLKS, 256>>>(Wq, Wk, Wv);

    cudaFuncSetAttribute(proj_gemm,
                         cudaFuncAttributeMaxDynamicSharedMemorySize, GM_SMEM_BYTES);

    // grid.x fastest = (proj, n-tile): X m-tile reused 24x from L2, W resident
    dim3 grid(3 * (D_MODEL / GM_BN), M_TOTAL / GM_BM);   // (24, 320)
    proj_gemm<<<grid, 256, GM_SMEM_BYTES>>>(X, bq, bk, bv);

    attn_kernel<<<BATCH * NHEADS, 128>>>(ln, (float*)d_out);
}

// round 14
// speedup vs baseline: 1.0277x; 1.0277x over previous
#include <cuda_runtime.h>
#include <cuda_fp16.h>
#include <cstdint>
#include <math.h>

// Problem constants
#define D_MODEL 1024
#define NHEADS  16
#define DK      64
#define BATCH   2048
#define SEQ     20
#define M_TOTAL (BATCH * SEQ)   // 40960

#define NCHUNK 4
#define MT_PER_CHUNK (M_TOTAL / 128 / NCHUNK)       // 80 m-tiles per chunk
#define BH_PER_CHUNK (BATCH * NHEADS / NCHUNK)      // 8192 attn blocks per chunk

// ---------------------------------------------------------------------------
// Scratch (fp16)
// ---------------------------------------------------------------------------
__device__ __half g_xh[(size_t)M_TOTAL * D_MODEL];
__device__ __half g_wh[3][(size_t)D_MODEL * D_MODEL];
__device__ __half g_qh[(size_t)M_TOTAL * D_MODEL];
__device__ __half g_kh[(size_t)M_TOTAL * D_MODEL];
__device__ __half g_vh[(size_t)M_TOTAL * D_MODEL];

// ---------------------------------------------------------------------------
// Merged fp32 -> fp16 conversion with streaming 16B loads/stores.
// ---------------------------------------------------------------------------
struct alignas(16) Half8 { __half2 a, b, c, d; };

#define XBLKS 10240
#define WBLKS 256

__global__ __launch_bounds__(256) void f2h_multi(
    const float* __restrict__ X,
    const float* __restrict__ Wq, const float* __restrict__ Wk, const float* __restrict__ Wv)
{
    const float* src;
    __half* dst;
    int local;
    if (blockIdx.x < XBLKS) {
        src = X; dst = g_xh; local = blockIdx.x;
    } else {
        int w = (blockIdx.x - XBLKS) / WBLKS;
        local = (blockIdx.x - XBLKS) % WBLKS;
        src = (w == 0) ? Wq : (w == 1) ? Wk : Wv;
        dst = &g_wh[w][0];
    }
    int c0 = (local * 256 + threadIdx.x) * 2;    // exact fit
    float4 v[4];
    #pragma unroll
    for (int u = 0; u < 4; u++)
        v[u] = __ldcs(&((const float4*)src)[c0 * 2 + u]);
    #pragma unroll
    for (int u = 0; u < 2; u++) {
        Half8 h;
        h.a = __floats2half2_rn(v[2 * u].x,     v[2 * u].y);
        h.b = __floats2half2_rn(v[2 * u].z,     v[2 * u].w);
        h.c = __floats2half2_rn(v[2 * u + 1].x, v[2 * u + 1].y);
        h.d = __floats2half2_rn(v[2 * u + 1].z, v[2 * u + 1].w);
        __stcs((float4*)&((Half8*)dst)[c0 + u], *(float4*)&h);
    }
}

// ---------------------------------------------------------------------------
// MMA / ldmatrix helpers
// ---------------------------------------------------------------------------
__device__ __forceinline__ void mma16(float* c, const uint32_t* a, const uint32_t* b) {
    asm volatile(
        "mma.sync.aligned.m16n8k16.row.col.f32.f16.f16.f32 "
        "{%0,%1,%2,%3}, {%4,%5,%6,%7}, {%8,%9}, {%0,%1,%2,%3};"
        : "+f"(c[0]), "+f"(c[1]), "+f"(c[2]), "+f"(c[3])
        : "r"(a[0]), "r"(a[1]), "r"(a[2]), "r"(a[3]),
          "r"(b[0]), "r"(b[1]));
}
__device__ __forceinline__ void ldmatrix_x4(uint32_t* r, uint32_t addr) {
    asm volatile("ldmatrix.sync.aligned.m8n8.x4.shared.b16 {%0,%1,%2,%3}, [%4];"
                 : "=r"(r[0]), "=r"(r[1]), "=r"(r[2]), "=r"(r[3]) : "r"(addr));
}
__device__ __forceinline__ void ldmatrix_x2(uint32_t* r, uint32_t addr) {
    asm volatile("ldmatrix.sync.aligned.m8n8.x2.shared.b16 {%0,%1}, [%2];"
                 : "=r"(r[0]), "=r"(r[1]) : "r"(addr));
}
__device__ __forceinline__ void cp16(uint32_t saddr, const void* g) {
    asm volatile("cp.async.cg.shared.global [%0], [%1], 16;\n" :: "r"(saddr), "l"(g));
}
#define CP_COMMIT() asm volatile("cp.async.commit_group;\n" ::: "memory")
#define CP_WAIT(n)  asm volatile("cp.async.wait_group %0;\n" :: "n"(n) : "memory")

__device__ __forceinline__ uint32_t smem_u32(const void* p) {
    uint32_t a;
    asm("{ .reg .u64 t; cvta.to.shared.u64 t, %1; cvt.u32.u64 %0, t; }"
        : "=r"(a) : "l"(p));
    return a;
}

// ---------------------------------------------------------------------------
// Projection GEMM (exact R7/R12 config): Y = X @ W^T + b, chunked over M.
// BM=128, BN=128, BK=32, 3-stage cp.async, 2 CTAs/SM.
// ---------------------------------------------------------------------------
#define GM_BM 128
#define GM_BN 128
#define GM_BK 32
#define WSTRIDE 20
#define A_STG_WORDS (GM_BM * WSTRIDE)     // 2560
#define B_STG_WORDS (GM_BN * WSTRIDE)     // 2560
#define STG_WORDS   (A_STG_WORDS + B_STG_WORDS)  // 5120
#define NSTAGE 3
#define GM_SMEM_BYTES (NSTAGE * STG_WORDS * 4)   // 61440
#define GM_KT (D_MODEL / GM_BK)           // 32

__global__ __launch_bounds__(256, 2) void proj_gemm(
    const float* __restrict__ bq, const float* __restrict__ bk, const float* __restrict__ bv,
    int mtOff)
{
    extern __shared__ uint32_t smem[];
    const uint32_t sb = smem_u32(smem);

    const int tid  = threadIdx.x;
    const int lane = tid & 31;
    const int warp = tid >> 5;
    const int wr   = warp >> 2;
    const int wc   = warp & 3;
    const int g    = lane >> 2;
    const int tq   = lane & 3;

    const int proj  = blockIdx.x >> 3;
    const int nBase = (blockIdx.x & 7) * GM_BN;
    const int mBase = (mtOff + blockIdx.y) * GM_BM;

    const __half* Wp = g_wh[proj];

    auto load_stage = [&](int stg, int kt) {
        uint32_t base = sb + stg * (STG_WORDS * 4);
        int k0 = kt * GM_BK;
        #pragma unroll
        for (int i = 0; i < 2; i++) {
            int ch = tid + i * 256;
            int r = ch >> 2, c = ch & 3;
            cp16(base + (r * WSTRIDE + c * 4) * 4,
                 &g_xh[(size_t)(mBase + r) * D_MODEL + k0 + c * 8]);
        }
        #pragma unroll
        for (int i = 0; i < 2; i++) {
            int ch = tid + i * 256;
            int r = ch >> 2, c = ch & 3;
            cp16(base + (A_STG_WORDS + r * WSTRIDE + c * 4) * 4,
                 &Wp[(size_t)(nBase + r) * D_MODEL + k0 + c * 8]);
        }
        CP_COMMIT();
    };

    float c[4][4][4];
    #pragma unroll
    for (int mt = 0; mt < 4; mt++)
        #pragma unroll
        for (int nt = 0; nt < 4; nt++)
            #pragma unroll
            for (int i = 0; i < 4; i++) c[mt][nt][i] = 0.f;

    load_stage(0, 0);
    load_stage(1, 1);

    for (int kt = 0; kt < GM_KT; kt++) {
        int stg = kt % NSTAGE;
        if (kt + 2 < GM_KT) load_stage((kt + 2) % NSTAGE, kt + 2);
        if (kt < GM_KT - 2)      CP_WAIT(2);
        else if (kt == GM_KT - 2) CP_WAIT(1);
        else                      CP_WAIT(0);
        __syncthreads();

        const uint32_t* sAw = smem + stg * STG_WORDS;
        const uint32_t* sBw = sAw + A_STG_WORDS;

        #pragma unroll
        for (int ks = 0; ks < 2; ks++) {
            const int kw = ks * 8 + tq;
            uint32_t af[4][4], bf[4][2];
            #pragma unroll
            for (int mt = 0; mt < 4; mt++) {
                int rb = (wr * 64 + mt * 16 + g) * WSTRIDE + kw;
                af[mt][0] = sAw[rb];
                af[mt][1] = sAw[rb + 8 * WSTRIDE];
                af[mt][2] = sAw[rb + 4];
                af[mt][3] = sAw[rb + 8 * WSTRIDE + 4];
            }
            #pragma unroll
            for (int nt = 0; nt < 4; nt++) {
                int rb = (wc * 32 + nt * 8 + g) * WSTRIDE + kw;
                bf[nt][0] = sBw[rb];
                bf[nt][1] = sBw[rb + 4];
            }
            #pragma unroll
            for (int mt = 0; mt < 4; mt++)
                #pragma unroll
                for (int nt = 0; nt < 4; nt++)
                    mma16(c[mt][nt], af[mt], bf[nt]);
        }
        __syncthreads();
    }

    const float* bp = (proj == 0) ? bq : (proj == 1) ? bk : bv;
    __half* outp    = (proj == 0) ? g_qh : (proj == 1) ? g_kh : g_vh;
    #pragma unroll
    for (int mt = 0; mt < 4; mt++) {
        #pragma unroll
        for (int nt = 0; nt < 4; nt++) {
            int row = mBase + wr * 64 + mt * 16 + g;
            int col = nBase + wc * 32 + nt * 8 + 2 * tq;
            float b0 = bp[col], b1 = bp[col + 1];
            __half2 h01 = __floats2half2_rn(c[mt][nt][0] + b0, c[mt][nt][1] + b1);
            __half2 h23 = __floats2half2_rn(c[mt][nt][2] + b0, c[mt][nt][3] + b1);
            *(__half2*)&outp[(size_t)row * D_MODEL + col] = h01;
            *(__half2*)&outp[(size_t)(row + 8) * D_MODEL + col] = h23;
        }
    }
}

// ---------------------------------------------------------------------------
// Attention + decay (R9/R12-validated), chunked over (b,h).
// Score phase on tensor cores; streaming output stores.
// ---------------------------------------------------------------------------
#define QK_STRIDE 72   // halves per row; 144 B = 9 x 16 B (ldmatrix-aligned)

__global__ __launch_bounds__(128) void attn_kernel(
    const int* __restrict__ lenbuf, float* __restrict__ out, int bhOff)
{
    const int bh = bhOff + blockIdx.x;
    const int b  = bh >> 4;
    const int h  = bh & 15;
    const int tid  = threadIdx.x;
    const int warp = tid >> 5;
    const int lane = tid & 31;

    __shared__ __align__(16) __half sqh[32][QK_STRIDE];
    __shared__ __align__(16) __half skh[24][QK_STRIDE];
    __shared__ __align__(16) float sv[SEQ][68];
    __shared__ float ssc[SEQ][24];
    __shared__ float sinv[SEQ];
    __shared__ __align__(16) float wgtT[SEQ][24];   // [j][i]

    for (int i = tid; i < 32 * (QK_STRIDE / 2); i += 128) ((uint32_t*)sqh)[i] = 0;
    for (int i = tid; i < 24 * (QK_STRIDE / 2); i += 128) ((uint32_t*)skh)[i] = 0;
    __syncthreads();

    {
        size_t base = (size_t)(b * SEQ) * D_MODEL + h * DK;
        for (int e = tid; e < SEQ * (DK / 8); e += 128) {
            int s = e >> 3, d8 = (e & 7) * 8;
            size_t gi = base + (size_t)s * D_MODEL + d8;
            Half8 q8 = *(const Half8*)&g_qh[gi];
            Half8 k8 = *(const Half8*)&g_kh[gi];
            Half8 v8 = *(const Half8*)&g_vh[gi];
            *(Half8*)&sqh[s][d8] = q8;
            *(Half8*)&skh[s][d8] = k8;
            float2 fa = __half22float2(v8.a), fb = __half22float2(v8.b);
            float2 fc = __half22float2(v8.c), fd = __half22float2(v8.d);
            *(float4*)&sv[s][d8]     = make_float4(fa.x, fa.y, fb.x, fb.y);
            *(float4*)&sv[s][d8 + 4] = make_float4(fc.x, fc.y, fd.x, fd.y);
        }
    }
    __syncthreads();

    // length may be int64 or int32 (jax x64 config). All lengths >= 1,
    // so int32-view word 1 == 0 iff buffer is int64.
    bool is64 = (lenbuf[1] == 0);
    int len = is64 ? lenbuf[2 * b] : lenbuf[b];

    if (warp < 3) {
        float c[2][4];
        #pragma unroll
        for (int mt = 0; mt < 2; mt++)
            #pragma unroll
            for (int i = 0; i < 4; i++) c[mt][i] = 0.f;

        const uint32_t sq_base = smem_u32(&sqh[0][0]);
        const uint32_t sk_base = smem_u32(&skh[0][0]);

        #pragma unroll
        for (int ks = 0; ks < 4; ks++) {
            uint32_t bfrag[2];
            {
                int l = lane & 15;
                int row = warp * 8 + (l & 7);
                int col = ks * 16 + ((l >> 3) & 1) * 8;
                ldmatrix_x2(bfrag, sk_base + (row * QK_STRIDE + col) * 2);
            }
            #pragma unroll
            for (int mt = 0; mt < 2; mt++) {
                uint32_t afrag[4];
                int row = mt * 16 + (lane & 15);
                int col = ks * 16 + (lane >> 4) * 8;
                ldmatrix_x4(afrag, sq_base + (row * QK_STRIDE + col) * 2);
                mma16(c[mt], afrag, bfrag);
            }
        }

        int jc = warp * 8 + 2 * (lane & 3);
        bool jv0 = (jc < SEQ), jv1 = (jc + 1 < SEQ);
        float m0 = (jc < len) ? 1.f : 0.f;
        float m1 = (jc + 1 < len) ? 1.f : 0.f;
        #pragma unroll
        for (int mt = 0; mt < 2; mt++) {
            #pragma unroll
            for (int hrow = 0; hrow < 2; hrow++) {
                int r = mt * 16 + (lane >> 2) + hrow * 8;
                if (r < SEQ) {
                    if (jv0) ssc[r][jc]     = m0 * __expf(c[mt][2 * hrow]     * 0.125f);
                    if (jv1) ssc[r][jc + 1] = m1 * __expf(c[mt][2 * hrow + 1] * 0.125f);
                }
            }
        }
    }
    __syncthreads();

    if (tid < SEQ) {
        float s = 0.f;
        #pragma unroll
        for (int j = 0; j < SEQ; j++) s += ssc[tid][j];
        sinv[tid] = 1.f / (s + 1e-8f);
    }
    __syncthreads();

    for (int e = tid; e < SEQ * SEQ; e += 128) {
        int i = e % SEQ, j = e / SEQ;
        wgtT[j][i] = ssc[i][j] * sinv[i] - (float)((i > j) ? (i - j) : (j - i));
    }
    __syncthreads();

    if (tid < 80) {
        int i0 = (tid / 16) * 4;
        int d0 = (tid & 15) * 4;
        float4 o0 = {0, 0, 0, 0}, o1 = {0, 0, 0, 0}, o2 = {0, 0, 0, 0}, o3 = {0, 0, 0, 0};
        #pragma unroll
        for (int j = 0; j < SEQ; j++) {
            float4 vv = *(const float4*)&sv[j][d0];
            float4 w  = *(const float4*)&wgtT[j][i0];
            o0.x += w.x * vv.x; o0.y += w.x * vv.y; o0.z += w.x * vv.z; o0.w += w.x * vv.w;
            o1.x += w.y * vv.x; o1.y += w.y * vv.y; o1.z += w.y * vv.z; o1.w += w.y * vv.w;
            o2.x += w.z * vv.x; o2.y += w.z * vv.y; o2.z += w.z * vv.z; o2.w += w.z * vv.w;
            o3.x += w.w * vv.x; o3.y += w.w * vv.y; o3.z += w.w * vv.z; o3.w += w.w * vv.w;
        }
        size_t base = (size_t)(b * SEQ + i0) * D_MODEL + h * DK + d0;
        __stcs((float4*)&out[base],               o0);
        __stcs((float4*)&out[base + D_MODEL],     o1);
        __stcs((float4*)&out[base + 2 * D_MODEL], o2);
        __stcs((float4*)&out[base + 3 * D_MODEL], o3);
    }
}

// ---------------------------------------------------------------------------
// Inputs (metadata order): Q, W_Q, b_Q, W_K, b_K, W_V, b_V, length
// Fork-join: gemm chunks on the captured (default) stream; attn chunks on a
// side stream gated per-chunk by events; join back at the end.
// ---------------------------------------------------------------------------
extern "C" void kernel_launch(void* const* d_in, const int* in_sizes, int n_in,
                              void* d_out, int out_size)
{
    const float* X  = (const float*)d_in[0];
    const float* Wq = (const float*)d_in[1];
    const float* bq = (const float*)d_in[2];
    const float* Wk = (const float*)d_in[3];
    const float* bk = (const float*)d_in[4];
    const float* Wv = (const float*)d_in[5];
    const float* bv = (const float*)d_in[6];
    const int*   ln = (const int*)d_in[7];

    static cudaStream_t s2 = nullptr;
    static cudaEvent_t evc[NCHUNK], evj;
    if (!s2) {
        cudaStreamCreateWithFlags(&s2, cudaStreamNonBlocking);
        for (int c = 0; c < NCHUNK; c++)
            cudaEventCreateWithFlags(&evc[c], cudaEventDisableTiming);
        cudaEventCreateWithFlags(&evj, cudaEventDisableTiming);
    }

    f2h_multi<<<XBLKS + 3 * WBLKS, 256>>>(X, Wq, Wk, Wv);

    cudaFuncSetAttribute(proj_gemm,
                         cudaFuncAttributeMaxDynamicSharedMemorySize, GM_SMEM_BYTES);

    dim3 ggrid(3 * (D_MODEL / GM_BN), MT_PER_CHUNK);   // (24, 80) per chunk
    for (int c = 0; c < NCHUNK; c++) {
        proj_gemm<<<ggrid, 256, GM_SMEM_BYTES>>>(bq, bk, bv, c * MT_PER_CHUNK);
        cudaEventRecord(evc[c], 0);
    }
    for (int c = 0; c < NCHUNK; c++) {
        cudaStreamWaitEvent(s2, evc[c], 0);
        attn_kernel<<<BH_PER_CHUNK, 128, 0, s2>>>(ln, (float*)d_out, c * BH_PER_CHUNK);
    }
    cudaEventRecord(evj, s2);
    cudaStreamWaitEvent(0, evj, 0);
}

// round 15
// speedup vs baseline: 1.0913x; 1.0618x over previous
#include <cuda_runtime.h>
#include <cuda_fp16.h>
#include <cstdint>
#include <math.h>

// Problem constants
#define D_MODEL 1024
#define NHEADS  16
#define DK      64
#define BATCH   2048
#define SEQ     20
#define M_TOTAL (BATCH * SEQ)   // 40960

#define NCHUNK 4
#define MT_PER_CHUNK (M_TOTAL / 128 / NCHUNK)       // 80 m-tiles per chunk
#define BH_PER_CHUNK (BATCH * NHEADS / NCHUNK)      // 8192 attn blocks per chunk

// ---------------------------------------------------------------------------
// Scratch (fp16)
// ---------------------------------------------------------------------------
__device__ __half g_xh[(size_t)M_TOTAL * D_MODEL];
__device__ __half g_wh[3][(size_t)D_MODEL * D_MODEL];
__device__ __half g_qh[(size_t)M_TOTAL * D_MODEL];
__device__ __half g_kh[(size_t)M_TOTAL * D_MODEL];
__device__ __half g_vh[(size_t)M_TOTAL * D_MODEL];

// ---------------------------------------------------------------------------
// Merged fp32 -> fp16 conversion with streaming 16B loads/stores.
// ---------------------------------------------------------------------------
struct alignas(16) Half8 { __half2 a, b, c, d; };

#define XBLKS 10240
#define WBLKS 256

__global__ __launch_bounds__(256) void f2h_multi(
    const float* __restrict__ X,
    const float* __restrict__ Wq, const float* __restrict__ Wk, const float* __restrict__ Wv)
{
    const float* src;
    __half* dst;
    int local;
    if (blockIdx.x < XBLKS) {
        src = X; dst = g_xh; local = blockIdx.x;
    } else {
        int w = (blockIdx.x - XBLKS) / WBLKS;
        local = (blockIdx.x - XBLKS) % WBLKS;
        src = (w == 0) ? Wq : (w == 1) ? Wk : Wv;
        dst = &g_wh[w][0];
    }
    int c0 = (local * 256 + threadIdx.x) * 2;    // exact fit
    float4 v[4];
    #pragma unroll
    for (int u = 0; u < 4; u++)
        v[u] = __ldcs(&((const float4*)src)[c0 * 2 + u]);
    #pragma unroll
    for (int u = 0; u < 2; u++) {
        Half8 h;
        h.a = __floats2half2_rn(v[2 * u].x,     v[2 * u].y);
        h.b = __floats2half2_rn(v[2 * u].z,     v[2 * u].w);
        h.c = __floats2half2_rn(v[2 * u + 1].x, v[2 * u + 1].y);
        h.d = __floats2half2_rn(v[2 * u + 1].z, v[2 * u + 1].w);
        __stcs((float4*)&((Half8*)dst)[c0 + u], *(float4*)&h);
    }
}

// ---------------------------------------------------------------------------
// MMA / ldmatrix helpers
// ---------------------------------------------------------------------------
__device__ __forceinline__ void mma16(float* c, const uint32_t* a, const uint32_t* b) {
    asm volatile(
        "mma.sync.aligned.m16n8k16.row.col.f32.f16.f16.f32 "
        "{%0,%1,%2,%3}, {%4,%5,%6,%7}, {%8,%9}, {%0,%1,%2,%3};"
        : "+f"(c[0]), "+f"(c[1]), "+f"(c[2]), "+f"(c[3])
        : "r"(a[0]), "r"(a[1]), "r"(a[2]), "r"(a[3]),
          "r"(b[0]), "r"(b[1]));
}
__device__ __forceinline__ void ldmatrix_x4(uint32_t* r, uint32_t addr) {
    asm volatile("ldmatrix.sync.aligned.m8n8.x4.shared.b16 {%0,%1,%2,%3}, [%4];"
                 : "=r"(r[0]), "=r"(r[1]), "=r"(r[2]), "=r"(r[3]) : "r"(addr));
}
__device__ __forceinline__ void ldmatrix_x2(uint32_t* r, uint32_t addr) {
    asm volatile("ldmatrix.sync.aligned.m8n8.x2.shared.b16 {%0,%1}, [%2];"
                 : "=r"(r[0]), "=r"(r[1]) : "r"(addr));
}
__device__ __forceinline__ void cp16(uint32_t saddr, const void* g) {
    asm volatile("cp.async.cg.shared.global [%0], [%1], 16;\n" :: "r"(saddr), "l"(g));
}
#define CP_COMMIT() asm volatile("cp.async.commit_group;\n" ::: "memory")
#define CP_WAIT(n)  asm volatile("cp.async.wait_group %0;\n" :: "n"(n) : "memory")

__device__ __forceinline__ uint32_t smem_u32(const void* p) {
    uint32_t a;
    asm("{ .reg .u64 t; cvta.to.shared.u64 t, %1; cvt.u32.u64 %0, t; }"
        : "=r"(a) : "l"(p));
    return a;
}

// ---------------------------------------------------------------------------
// Projection GEMM: Y = X @ W^T + b, chunked over M. 2 CTAs/SM.
// BM=128, BN=128, BK=32, 3-stage cp.async.
// Fragment loads via ldmatrix (A: x4 per mt, B: x2 per nt) — the lane->(row,
// col) mappings are the ones validated in the R9 attn kernel. Rows of the
// 20-word-stride smem layout map 8 consecutive rows onto banks
// {0,20,8,28,16,4,24,12}+c — each ldmatrix phase covers all 32 banks:
// conflict-free.
// ---------------------------------------------------------------------------
#define GM_BM 128
#define GM_BN 128
#define GM_BK 32
#define WSTRIDE 20                         // words per row (= 40 halves)
#define A_STG_WORDS (GM_BM * WSTRIDE)     // 2560
#define B_STG_WORDS (GM_BN * WSTRIDE)     // 2560
#define STG_WORDS   (A_STG_WORDS + B_STG_WORDS)  // 5120
#define NSTAGE 3
#define GM_SMEM_BYTES (NSTAGE * STG_WORDS * 4)   // 61440
#define GM_KT (D_MODEL / GM_BK)           // 32

__global__ __launch_bounds__(256, 2) void proj_gemm(
    const float* __restrict__ bq, const float* __restrict__ bk, const float* __restrict__ bv,
    int mtOff)
{
    extern __shared__ uint32_t smem[];
    const uint32_t sb = smem_u32(smem);

    const int tid  = threadIdx.x;
    const int lane = tid & 31;
    const int warp = tid >> 5;
    const int wr   = warp >> 2;
    const int wc   = warp & 3;
    const int g    = lane >> 2;
    const int tq   = lane & 3;

    const int proj  = blockIdx.x >> 3;
    const int nBase = (blockIdx.x & 7) * GM_BN;
    const int mBase = (mtOff + blockIdx.y) * GM_BM;

    const __half* Wp = g_wh[proj];

    auto load_stage = [&](int stg, int kt) {
        uint32_t base = sb + stg * (STG_WORDS * 4);
        int k0 = kt * GM_BK;
        #pragma unroll
        for (int i = 0; i < 2; i++) {
            int ch = tid + i * 256;
            int r = ch >> 2, c = ch & 3;
            cp16(base + (r * WSTRIDE + c * 4) * 4,
                 &g_xh[(size_t)(mBase + r) * D_MODEL + k0 + c * 8]);
        }
        #pragma unroll
        for (int i = 0; i < 2; i++) {
            int ch = tid + i * 256;
            int r = ch >> 2, c = ch & 3;
            cp16(base + (A_STG_WORDS + r * WSTRIDE + c * 4) * 4,
                 &Wp[(size_t)(nBase + r) * D_MODEL + k0 + c * 8]);
        }
        CP_COMMIT();
    };

    float c[4][4][4];
    #pragma unroll
    for (int mt = 0; mt < 4; mt++)
        #pragma unroll
        for (int nt = 0; nt < 4; nt++)
            #pragma unroll
            for (int i = 0; i < 4; i++) c[mt][nt][i] = 0.f;

    load_stage(0, 0);
    load_stage(1, 1);

    // ldmatrix lane row/col components (halves)
    const int aRow = (lane & 15);             // within 16-row A tile
    const int aCol = (lane >> 4) * 8;         // 0 or 8
    const int bRow = (lane & 7);              // within 8-row B tile
    const int bCol = ((lane >> 3) & 1) * 8;   // 0 or 8

    for (int kt = 0; kt < GM_KT; kt++) {
        int stg = kt % NSTAGE;
        if (kt + 2 < GM_KT) load_stage((kt + 2) % NSTAGE, kt + 2);
        if (kt < GM_KT - 2)      CP_WAIT(2);
        else if (kt == GM_KT - 2) CP_WAIT(1);
        else                      CP_WAIT(0);
        __syncthreads();

        const uint32_t sA = sb + stg * (STG_WORDS * 4);
        const uint32_t sB = sA + A_STG_WORDS * 4;

        #pragma unroll
        for (int ks = 0; ks < 2; ks++) {
            uint32_t af[4][4], bf[4][2];
            #pragma unroll
            for (int mt = 0; mt < 4; mt++) {
                int row = wr * 64 + mt * 16 + aRow;
                int col = ks * 16 + aCol;
                ldmatrix_x4(af[mt], sA + (row * 40 + col) * 2);
            }
            #pragma unroll
            for (int nt = 0; nt < 4; nt++) {
                int row = wc * 32 + nt * 8 + bRow;
                int col = ks * 16 + bCol;
                ldmatrix_x2(bf[nt], sB + (row * 40 + col) * 2);
            }
            #pragma unroll
            for (int mt = 0; mt < 4; mt++)
                #pragma unroll
                for (int nt = 0; nt < 4; nt++)
                    mma16(c[mt][nt], af[mt], bf[nt]);
        }
        __syncthreads();
    }

    const float* bp = (proj == 0) ? bq : (proj == 1) ? bk : bv;
    __half* outp    = (proj == 0) ? g_qh : (proj == 1) ? g_kh : g_vh;
    #pragma unroll
    for (int mt = 0; mt < 4; mt++) {
        #pragma unroll
        for (int nt = 0; nt < 4; nt++) {
            int row = mBase + wr * 64 + mt * 16 + g;
            int col = nBase + wc * 32 + nt * 8 + 2 * tq;
            float b0 = bp[col], b1 = bp[col + 1];
            __half2 h01 = __floats2half2_rn(c[mt][nt][0] + b0, c[mt][nt][1] + b1);
            __half2 h23 = __floats2half2_rn(c[mt][nt][2] + b0, c[mt][nt][3] + b1);
            *(__half2*)&outp[(size_t)row * D_MODEL + col] = h01;
            *(__half2*)&outp[(size_t)(row + 8) * D_MODEL + col] = h23;
        }
    }
}

// ---------------------------------------------------------------------------
// Attention + decay (R9/R12-validated), chunked over (b,h).
// ---------------------------------------------------------------------------
#define QK_STRIDE 72   // halves per row; 144 B = 9 x 16 B (ldmatrix-aligned)

__global__ __launch_bounds__(128) void attn_kernel(
    const int* __restrict__ lenbuf, float* __restrict__ out, int bhOff)
{
    const int bh = bhOff + blockIdx.x;
    const int b  = bh >> 4;
    const int h  = bh & 15;
    const int tid  = threadIdx.x;
    const int warp = tid >> 5;
    const int lane = tid & 31;

    __shared__ __align__(16) __half sqh[32][QK_STRIDE];
    __shared__ __align__(16) __half skh[24][QK_STRIDE];
    __shared__ __align__(16) float sv[SEQ][68];
    __shared__ float ssc[SEQ][24];
    __shared__ float sinv[SEQ];
    __shared__ __align__(16) float wgtT[SEQ][24];   // [j][i]

    for (int i = tid; i < 32 * (QK_STRIDE / 2); i += 128) ((uint32_t*)sqh)[i] = 0;
    for (int i = tid; i < 24 * (QK_STRIDE / 2); i += 128) ((uint32_t*)skh)[i] = 0;
    __syncthreads();

    {
        size_t base = (size_t)(b * SEQ) * D_MODEL + h * DK;
        for (int e = tid; e < SEQ * (DK / 8); e += 128) {
            int s = e >> 3, d8 = (e & 7) * 8;
            size_t gi = base + (size_t)s * D_MODEL + d8;
            Half8 q8 = *(const Half8*)&g_qh[gi];
            Half8 k8 = *(const Half8*)&g_kh[gi];
            Half8 v8 = *(const Half8*)&g_vh[gi];
            *(Half8*)&sqh[s][d8] = q8;
            *(Half8*)&skh[s][d8] = k8;
            float2 fa = __half22float2(v8.a), fb = __half22float2(v8.b);
            float2 fc = __half22float2(v8.c), fd = __half22float2(v8.d);
            *(float4*)&sv[s][d8]     = make_float4(fa.x, fa.y, fb.x, fb.y);
            *(float4*)&sv[s][d8 + 4] = make_float4(fc.x, fc.y, fd.x, fd.y);
        }
    }
    __syncthreads();

    // length may be int64 or int32 (jax x64 config). All lengths >= 1,
    // so int32-view word 1 == 0 iff buffer is int64.
    bool is64 = (lenbuf[1] == 0);
    int len = is64 ? lenbuf[2 * b] : lenbuf[b];

    if (warp < 3) {
        float c[2][4];
        #pragma unroll
        for (int mt = 0; mt < 2; mt++)
            #pragma unroll
            for (int i = 0; i < 4; i++) c[mt][i] = 0.f;

        const uint32_t sq_base = smem_u32(&sqh[0][0]);
        const uint32_t sk_base = smem_u32(&skh[0][0]);

        #pragma unroll
        for (int ks = 0; ks < 4; ks++) {
            uint32_t bfrag[2];
            {
                int l = lane & 15;
                int row = warp * 8 + (l & 7);
                int col = ks * 16 + ((l >> 3) & 1) * 8;
                ldmatrix_x2(bfrag, sk_base + (row * QK_STRIDE + col) * 2);
            }
            #pragma unroll
            for (int mt = 0; mt < 2; mt++) {
                uint32_t afrag[4];
                int row = mt * 16 + (lane & 15);
                int col = ks * 16 + (lane >> 4) * 8;
                ldmatrix_x4(afrag, sq_base + (row * QK_STRIDE + col) * 2);
                mma16(c[mt], afrag, bfrag);
            }
        }

        int jc = warp * 8 + 2 * (lane & 3);
        bool jv0 = (jc < SEQ), jv1 = (jc + 1 < SEQ);
        float m0 = (jc < len) ? 1.f : 0.f;
        float m1 = (jc + 1 < len) ? 1.f : 0.f;
        #pragma unroll
        for (int mt = 0; mt < 2; mt++) {
            #pragma unroll
            for (int hrow = 0; hrow < 2; hrow++) {
                int r = mt * 16 + (lane >> 2) + hrow * 8;
                if (r < SEQ) {
                    if (jv0) ssc[r][jc]     = m0 * __expf(c[mt][2 * hrow]     * 0.125f);
                    if (jv1) ssc[r][jc + 1] = m1 * __expf(c[mt][2 * hrow + 1] * 0.125f);
                }
            }
        }
    }
    __syncthreads();

    if (tid < SEQ) {
        float s = 0.f;
        #pragma unroll
        for (int j = 0; j < SEQ; j++) s += ssc[tid][j];
        sinv[tid] = 1.f / (s + 1e-8f);
    }
    __syncthreads();

    for (int e = tid; e < SEQ * SEQ; e += 128) {
        int i = e % SEQ, j = e / SEQ;
        wgtT[j][i] = ssc[i][j] * sinv[i] - (float)((i > j) ? (i - j) : (j - i));
    }
    __syncthreads();

    if (tid < 80) {
        int i0 = (tid / 16) * 4;
        int d0 = (tid & 15) * 4;
        float4 o0 = {0, 0, 0, 0}, o1 = {0, 0, 0, 0}, o2 = {0, 0, 0, 0}, o3 = {0, 0, 0, 0};
        #pragma unroll
        for (int j = 0; j < SEQ; j++) {
            float4 vv = *(const float4*)&sv[j][d0];
            float4 w  = *(const float4*)&wgtT[j][i0];
            o0.x += w.x * vv.x; o0.y += w.x * vv.y; o0.z += w.x * vv.z; o0.w += w.x * vv.w;
            o1.x += w.y * vv.x; o1.y += w.y * vv.y; o1.z += w.y * vv.z; o1.w += w.y * vv.w;
            o2.x += w.z * vv.x; o2.y += w.z * vv.y; o2.z += w.z * vv.z; o2.w += w.z * vv.w;
            o3.x += w.w * vv.x; o3.y += w.w * vv.y; o3.z += w.w * vv.z; o3.w += w.w * vv.w;
        }
        size_t base = (size_t)(b * SEQ + i0) * D_MODEL + h * DK + d0;
        __stcs((float4*)&out[base],               o0);
        __stcs((float4*)&out[base + D_MODEL],     o1);
        __stcs((float4*)&out[base + 2 * D_MODEL], o2);
        __stcs((float4*)&out[base + 3 * D_MODEL], o3);
    }
}

// ---------------------------------------------------------------------------
// Inputs (metadata order): Q, W_Q, b_Q, W_K, b_K, W_V, b_V, length
// Fork-join overlap: gemm chunks on captured stream, attn chunks on s2.
// ---------------------------------------------------------------------------
extern "C" void kernel_launch(void* const* d_in, const int* in_sizes, int n_in,
                              void* d_out, int out_size)
{
    const float* X  = (const float*)d_in[0];
    const float* Wq = (const float*)d_in[1];
    const float* bq = (const float*)d_in[2];
    const float* Wk = (const float*)d_in[3];
    const float* bk = (const float*)d_in[4];
    const float* Wv = (const float*)d_in[5];
    const float* bv = (const float*)d_in[6];
    const int*   ln = (const int*)d_in[7];

    static cudaStream_t s2 = nullptr;
    static cudaEvent_t evc[NCHUNK], evj;
    if (!s2) {
        cudaStreamCreateWithFlags(&s2, cudaStreamNonBlocking);
        for (int c = 0; c < NCHUNK; c++)
            cudaEventCreateWithFlags(&evc[c], cudaEventDisableTiming);
        cudaEventCreateWithFlags(&evj, cudaEventDisableTiming);
    }

    f2h_multi<<<XBLKS + 3 * WBLKS, 256>>>(X, Wq, Wk, Wv);

    cudaFuncSetAttribute(proj_gemm,
                         cudaFuncAttributeMaxDynamicSharedMemorySize, GM_SMEM_BYTES);

    dim3 ggrid(3 * (D_MODEL / GM_BN), MT_PER_CHUNK);   // (24, 80) per chunk
    for (int c = 0; c < NCHUNK; c++) {
        proj_gemm<<<ggrid, 256, GM_SMEM_BYTES>>>(bq, bk, bv, c * MT_PER_CHUNK);
        cudaEventRecord(evc[c], 0);
    }
    for (int c = 0; c < NCHUNK; c++) {
        cudaStreamWaitEvent(s2, evc[c], 0);
        attn_kernel<<<BH_PER_CHUNK, 128, 0, s2>>>(ln, (float*)d_out, c * BH_PER_CHUNK);
    }
    cudaEventRecord(evj, s2);
    cudaStreamWaitEvent(0, evj, 0);
}

// round 16
// speedup vs baseline: 1.0942x; 1.0027x over previous
#include <cuda_runtime.h>
#include <cuda_fp16.h>
#include <cstdint>
#include <math.h>

// Problem constants
#define D_MODEL 1024
#define NHEADS  16
#define DK      64
#define BATCH   2048
#define SEQ     20
#define M_TOTAL (BATCH * SEQ)   // 40960

// Wave-exact chunking: 2 CTAs/SM x 148 SMs = 296 concurrent CTAs.
// GEMM chunk of 74 m-tiles -> 24*74 = 1776 CTAs = exactly 6 waves.
#define NCHUNK 5
__constant__ int c_dummy;   // (unused)

// ---------------------------------------------------------------------------
// Scratch (fp16)
// ---------------------------------------------------------------------------
__device__ __half g_xh[(size_t)M_TOTAL * D_MODEL];
__device__ __half g_wh[3][(size_t)D_MODEL * D_MODEL];
__device__ __half g_qh[(size_t)M_TOTAL * D_MODEL];
__device__ __half g_kh[(size_t)M_TOTAL * D_MODEL];
__device__ __half g_vh[(size_t)M_TOTAL * D_MODEL];

// ---------------------------------------------------------------------------
// Merged fp32 -> fp16 conversion with streaming 16B loads/stores.
// ---------------------------------------------------------------------------
struct alignas(16) Half8 { __half2 a, b, c, d; };

#define XBLKS 10240
#define WBLKS 256

__global__ __launch_bounds__(256) void f2h_multi(
    const float* __restrict__ X,
    const float* __restrict__ Wq, const float* __restrict__ Wk, const float* __restrict__ Wv)
{
    const float* src;
    __half* dst;
    int local;
    if (blockIdx.x < XBLKS) {
        src = X; dst = g_xh; local = blockIdx.x;
    } else {
        int w = (blockIdx.x - XBLKS) / WBLKS;
        local = (blockIdx.x - XBLKS) % WBLKS;
        src = (w == 0) ? Wq : (w == 1) ? Wk : Wv;
        dst = &g_wh[w][0];
    }
    int c0 = (local * 256 + threadIdx.x) * 2;    // exact fit
    float4 v[4];
    #pragma unroll
    for (int u = 0; u < 4; u++)
        v[u] = __ldcs(&((const float4*)src)[c0 * 2 + u]);
    #pragma unroll
    for (int u = 0; u < 2; u++) {
        Half8 h;
        h.a = __floats2half2_rn(v[2 * u].x,     v[2 * u].y);
        h.b = __floats2half2_rn(v[2 * u].z,     v[2 * u].w);
        h.c = __floats2half2_rn(v[2 * u + 1].x, v[2 * u + 1].y);
        h.d = __floats2half2_rn(v[2 * u + 1].z, v[2 * u + 1].w);
        __stcs((float4*)&((Half8*)dst)[c0 + u], *(float4*)&h);
    }
}

// ---------------------------------------------------------------------------
// MMA / ldmatrix helpers
// ---------------------------------------------------------------------------
__device__ __forceinline__ void mma16(float* c, const uint32_t* a, const uint32_t* b) {
    asm volatile(
        "mma.sync.aligned.m16n8k16.row.col.f32.f16.f16.f32 "
        "{%0,%1,%2,%3}, {%4,%5,%6,%7}, {%8,%9}, {%0,%1,%2,%3};"
        : "+f"(c[0]), "+f"(c[1]), "+f"(c[2]), "+f"(c[3])
        : "r"(a[0]), "r"(a[1]), "r"(a[2]), "r"(a[3]),
          "r"(b[0]), "r"(b[1]));
}
__device__ __forceinline__ void ldmatrix_x4(uint32_t* r, uint32_t addr) {
    asm volatile("ldmatrix.sync.aligned.m8n8.x4.shared.b16 {%0,%1,%2,%3}, [%4];"
                 : "=r"(r[0]), "=r"(r[1]), "=r"(r[2]), "=r"(r[3]) : "r"(addr));
}
__device__ __forceinline__ void ldmatrix_x2(uint32_t* r, uint32_t addr) {
    asm volatile("ldmatrix.sync.aligned.m8n8.x2.shared.b16 {%0,%1}, [%2];"
                 : "=r"(r[0]), "=r"(r[1]) : "r"(addr));
}
__device__ __forceinline__ void cp16(uint32_t saddr, const void* g) {
    asm volatile("cp.async.cg.shared.global [%0], [%1], 16;\n" :: "r"(saddr), "l"(g));
}
#define CP_COMMIT() asm volatile("cp.async.commit_group;\n" ::: "memory")
#define CP_WAIT(n)  asm volatile("cp.async.wait_group %0;\n" :: "n"(n) : "memory")

__device__ __forceinline__ uint32_t smem_u32(const void* p) {
    uint32_t a;
    asm("{ .reg .u64 t; cvta.to.shared.u64 t, %1; cvt.u32.u64 %0, t; }"
        : "=r"(a) : "l"(p));
    return a;
}

// ---------------------------------------------------------------------------
// Projection GEMM (R15 ldmatrix version): Y = X @ W^T + b, chunked over M.
// BM=128, BN=128, BK=32, 3-stage cp.async, 2 CTAs/SM.
// ---------------------------------------------------------------------------
#define GM_BM 128
#define GM_BN 128
#define GM_BK 32
#define WSTRIDE 20                         // words per row (= 40 halves)
#define A_STG_WORDS (GM_BM * WSTRIDE)     // 2560
#define B_STG_WORDS (GM_BN * WSTRIDE)     // 2560
#define STG_WORDS   (A_STG_WORDS + B_STG_WORDS)  // 5120
#define NSTAGE 3
#define GM_SMEM_BYTES (NSTAGE * STG_WORDS * 4)   // 61440
#define GM_KT (D_MODEL / GM_BK)           // 32

__global__ __launch_bounds__(256, 2) void proj_gemm(
    const float* __restrict__ bq, const float* __restrict__ bk, const float* __restrict__ bv,
    int mtOff)
{
    extern __shared__ uint32_t smem[];
    const uint32_t sb = smem_u32(smem);

    const int tid  = threadIdx.x;
    const int lane = tid & 31;
    const int warp = tid >> 5;
    const int wr   = warp >> 2;
    const int wc   = warp & 3;
    const int g    = lane >> 2;
    const int tq   = lane & 3;

    const int proj  = blockIdx.x >> 3;
    const int nBase = (blockIdx.x & 7) * GM_BN;
    const int mBase = (mtOff + blockIdx.y) * GM_BM;

    const __half* Wp = g_wh[proj];

    auto load_stage = [&](int stg, int kt) {
        uint32_t base = sb + stg * (STG_WORDS * 4);
        int k0 = kt * GM_BK;
        #pragma unroll
        for (int i = 0; i < 2; i++) {
            int ch = tid + i * 256;
            int r = ch >> 2, c = ch & 3;
            cp16(base + (r * WSTRIDE + c * 4) * 4,
                 &g_xh[(size_t)(mBase + r) * D_MODEL + k0 + c * 8]);
        }
        #pragma unroll
        for (int i = 0; i < 2; i++) {
            int ch = tid + i * 256;
            int r = ch >> 2, c = ch & 3;
            cp16(base + (A_STG_WORDS + r * WSTRIDE + c * 4) * 4,
                 &Wp[(size_t)(nBase + r) * D_MODEL + k0 + c * 8]);
        }
        CP_COMMIT();
    };

    float c[4][4][4];
    #pragma unroll
    for (int mt = 0; mt < 4; mt++)
        #pragma unroll
        for (int nt = 0; nt < 4; nt++)
            #pragma unroll
            for (int i = 0; i < 4; i++) c[mt][nt][i] = 0.f;

    load_stage(0, 0);
    load_stage(1, 1);

    const int aRow = (lane & 15);
    const int aCol = (lane >> 4) * 8;
    const int bRow = (lane & 7);
    const int bCol = ((lane >> 3) & 1) * 8;

    for (int kt = 0; kt < GM_KT; kt++) {
        int stg = kt % NSTAGE;
        if (kt + 2 < GM_KT) load_stage((kt + 2) % NSTAGE, kt + 2);
        if (kt < GM_KT - 2)      CP_WAIT(2);
        else if (kt == GM_KT - 2) CP_WAIT(1);
        else                      CP_WAIT(0);
        __syncthreads();

        const uint32_t sA = sb + stg * (STG_WORDS * 4);
        const uint32_t sB = sA + A_STG_WORDS * 4;

        #pragma unroll
        for (int ks = 0; ks < 2; ks++) {
            uint32_t af[4][4], bf[4][2];
            #pragma unroll
            for (int mt = 0; mt < 4; mt++) {
                int row = wr * 64 + mt * 16 + aRow;
                int col = ks * 16 + aCol;
                ldmatrix_x4(af[mt], sA + (row * 40 + col) * 2);
            }
            #pragma unroll
            for (int nt = 0; nt < 4; nt++) {
                int row = wc * 32 + nt * 8 + bRow;
                int col = ks * 16 + bCol;
                ldmatrix_x2(bf[nt], sB + (row * 40 + col) * 2);
            }
            #pragma unroll
            for (int mt = 0; mt < 4; mt++)
                #pragma unroll
                for (int nt = 0; nt < 4; nt++)
                    mma16(c[mt][nt], af[mt], bf[nt]);
        }
        __syncthreads();
    }

    const float* bp = (proj == 0) ? bq : (proj == 1) ? bk : bv;
    __half* outp    = (proj == 0) ? g_qh : (proj == 1) ? g_kh : g_vh;
    #pragma unroll
    for (int mt = 0; mt < 4; mt++) {
        #pragma unroll
        for (int nt = 0; nt < 4; nt++) {
            int row = mBase + wr * 64 + mt * 16 + g;
            int col = nBase + wc * 32 + nt * 8 + 2 * tq;
            float b0 = bp[col], b1 = bp[col + 1];
            __half2 h01 = __floats2half2_rn(c[mt][nt][0] + b0, c[mt][nt][1] + b1);
            __half2 h23 = __floats2half2_rn(c[mt][nt][2] + b0, c[mt][nt][3] + b1);
            *(__half2*)&outp[(size_t)row * D_MODEL + col] = h01;
            *(__half2*)&outp[(size_t)(row + 8) * D_MODEL + col] = h23;
        }
    }
}

// ---------------------------------------------------------------------------
// Attention + decay (R9/R12-validated), chunked over (b,h).
// ---------------------------------------------------------------------------
#define QK_STRIDE 72   // halves per row; 144 B = 9 x 16 B (ldmatrix-aligned)

__global__ __launch_bounds__(128) void attn_kernel(
    const int* __restrict__ lenbuf, float* __restrict__ out, int bhOff)
{
    const int bh = bhOff + blockIdx.x;
    const int b  = bh >> 4;
    const int h  = bh & 15;
    const int tid  = threadIdx.x;
    const int warp = tid >> 5;
    const int lane = tid & 31;

    __shared__ __align__(16) __half sqh[32][QK_STRIDE];
    __shared__ __align__(16) __half skh[24][QK_STRIDE];
    __shared__ __align__(16) float sv[SEQ][68];
    __shared__ float ssc[SEQ][24];
    __shared__ float sinv[SEQ];
    __shared__ __align__(16) float wgtT[SEQ][24];   // [j][i]

    for (int i = tid; i < 32 * (QK_STRIDE / 2); i += 128) ((uint32_t*)sqh)[i] = 0;
    for (int i = tid; i < 24 * (QK_STRIDE / 2); i += 128) ((uint32_t*)skh)[i] = 0;
    __syncthreads();

    {
        size_t base = (size_t)(b * SEQ) * D_MODEL + h * DK;
        for (int e = tid; e < SEQ * (DK / 8); e += 128) {
            int s = e >> 3, d8 = (e & 7) * 8;
            size_t gi = base + (size_t)s * D_MODEL + d8;
            Half8 q8 = *(const Half8*)&g_qh[gi];
            Half8 k8 = *(const Half8*)&g_kh[gi];
            Half8 v8 = *(const Half8*)&g_vh[gi];
            *(Half8*)&sqh[s][d8] = q8;
            *(Half8*)&skh[s][d8] = k8;
            float2 fa = __half22float2(v8.a), fb = __half22float2(v8.b);
            float2 fc = __half22float2(v8.c), fd = __half22float2(v8.d);
            *(float4*)&sv[s][d8]     = make_float4(fa.x, fa.y, fb.x, fb.y);
            *(float4*)&sv[s][d8 + 4] = make_float4(fc.x, fc.y, fd.x, fd.y);
        }
    }
    __syncthreads();

    // length may be int64 or int32 (jax x64 config). All lengths >= 1,
    // so int32-view word 1 == 0 iff buffer is int64.
    bool is64 = (lenbuf[1] == 0);
    int len = is64 ? lenbuf[2 * b] : lenbuf[b];

    if (warp < 3) {
        float c[2][4];
        #pragma unroll
        for (int mt = 0; mt < 2; mt++)
            #pragma unroll
            for (int i = 0; i < 4; i++) c[mt][i] = 0.f;

        const uint32_t sq_base = smem_u32(&sqh[0][0]);
        const uint32_t sk_base = smem_u32(&skh[0][0]);

        #pragma unroll
        for (int ks = 0; ks < 4; ks++) {
            uint32_t bfrag[2];
            {
                int l = lane & 15;
                int row = warp * 8 + (l & 7);
                int col = ks * 16 + ((l >> 3) & 1) * 8;
                ldmatrix_x2(bfrag, sk_base + (row * QK_STRIDE + col) * 2);
            }
            #pragma unroll
            for (int mt = 0; mt < 2; mt++) {
                uint32_t afrag[4];
                int row = mt * 16 + (lane & 15);
                int col = ks * 16 + (lane >> 4) * 8;
                ldmatrix_x4(afrag, sq_base + (row * QK_STRIDE + col) * 2);
                mma16(c[mt], afrag, bfrag);
            }
        }

        int jc = warp * 8 + 2 * (lane & 3);
        bool jv0 = (jc < SEQ), jv1 = (jc + 1 < SEQ);
        float m0 = (jc < len) ? 1.f : 0.f;
        float m1 = (jc + 1 < len) ? 1.f : 0.f;
        #pragma unroll
        for (int mt = 0; mt < 2; mt++) {
            #pragma unroll
            for (int hrow = 0; hrow < 2; hrow++) {
                int r = mt * 16 + (lane >> 2) + hrow * 8;
                if (r < SEQ) {
                    if (jv0) ssc[r][jc]     = m0 * __expf(c[mt][2 * hrow]     * 0.125f);
                    if (jv1) ssc[r][jc + 1] = m1 * __expf(c[mt][2 * hrow + 1] * 0.125f);
                }
            }
        }
    }
    __syncthreads();

    if (tid < SEQ) {
        float s = 0.f;
        #pragma unroll
        for (int j = 0; j < SEQ; j++) s += ssc[tid][j];
        sinv[tid] = 1.f / (s + 1e-8f);
    }
    __syncthreads();

    for (int e = tid; e < SEQ * SEQ; e += 128) {
        int i = e % SEQ, j = e / SEQ;
        wgtT[j][i] = ssc[i][j] * sinv[i] - (float)((i > j) ? (i - j) : (j - i));
    }
    __syncthreads();

    if (tid < 80) {
        int i0 = (tid / 16) * 4;
        int d0 = (tid & 15) * 4;
        float4 o0 = {0, 0, 0, 0}, o1 = {0, 0, 0, 0}, o2 = {0, 0, 0, 0}, o3 = {0, 0, 0, 0};
        #pragma unroll
        for (int j = 0; j < SEQ; j++) {
            float4 vv = *(const float4*)&sv[j][d0];
            float4 w  = *(const float4*)&wgtT[j][i0];
            o0.x += w.x * vv.x; o0.y += w.x * vv.y; o0.z += w.x * vv.z; o0.w += w.x * vv.w;
            o1.x += w.y * vv.x; o1.y += w.y * vv.y; o1.z += w.y * vv.z; o1.w += w.y * vv.w;
            o2.x += w.z * vv.x; o2.y += w.z * vv.y; o2.z += w.z * vv.z; o2.w += w.z * vv.w;
            o3.x += w.w * vv.x; o3.y += w.w * vv.y; o3.z += w.w * vv.z; o3.w += w.w * vv.w;
        }
        size_t base = (size_t)(b * SEQ + i0) * D_MODEL + h * DK + d0;
        __stcs((float4*)&out[base],               o0);
        __stcs((float4*)&out[base + D_MODEL],     o1);
        __stcs((float4*)&out[base + 2 * D_MODEL], o2);
        __stcs((float4*)&out[base + 3 * D_MODEL], o3);
    }
}

// ---------------------------------------------------------------------------
// Inputs (metadata order): Q, W_Q, b_Q, W_K, b_K, W_V, b_V, length
// Wave-exact fork-join overlap:
//   GEMM chunks of {74,74,74,74,24} m-tiles (74 -> 1776 CTAs = 6.0 waves
//   exactly at 2 CTAs/SM x 148 SMs). Attn chunk c covers sequences whose 20
//   rows are fully within the cumulative computed rows.
// ---------------------------------------------------------------------------
extern "C" void kernel_launch(void* const* d_in, const int* in_sizes, int n_in,
                              void* d_out, int out_size)
{
    const float* X  = (const float*)d_in[0];
    const float* Wq = (const float*)d_in[1];
    const float* bq = (const float*)d_in[2];
    const float* Wk = (const float*)d_in[3];
    const float* bk = (const float*)d_in[4];
    const float* Wv = (const float*)d_in[5];
    const float* bv = (const float*)d_in[6];
    const int*   ln = (const int*)d_in[7];

    static const int mtSize[NCHUNK] = {74, 74, 74, 74, 24};
    static const int mtOff[NCHUNK]  = {0, 74, 148, 222, 296};
    // cumulative rows: 9472, 18944, 28416, 37888, 40960 -> b ends:
    static const int bEnd[NCHUNK]   = {473, 947, 1420, 1894, 2048};

    static cudaStream_t s2 = nullptr;
    static cudaEvent_t evc[NCHUNK], evj;
    if (!s2) {
        cudaStreamCreateWithFlags(&s2, cudaStreamNonBlocking);
        for (int c = 0; c < NCHUNK; c++)
            cudaEventCreateWithFlags(&evc[c], cudaEventDisableTiming);
        cudaEventCreateWithFlags(&evj, cudaEventDisableTiming);
    }

    f2h_multi<<<XBLKS + 3 * WBLKS, 256>>>(X, Wq, Wk, Wv);

    cudaFuncSetAttribute(proj_gemm,
                         cudaFuncAttributeMaxDynamicSharedMemorySize, GM_SMEM_BYTES);

    for (int c = 0; c < NCHUNK; c++) {
        dim3 ggrid(3 * (D_MODEL / GM_BN), mtSize[c]);
        proj_gemm<<<ggrid, 256, GM_SMEM_BYTES>>>(bq, bk, bv, mtOff[c]);
        cudaEventRecord(evc[c], 0);
    }
    int bStart = 0;
    for (int c = 0; c < NCHUNK; c++) {
        cudaStreamWaitEvent(s2, evc[c], 0);
        int nbh = (bEnd[c] - bStart) * NHEADS;
        attn_kernel<<<nbh, 128, 0, s2>>>(ln, (float*)d_out, bStart * NHEADS);
        bStart = bEnd[c];
    }
    cudaEventRecord(evj, s2);
    cudaStreamWaitEvent(0, evj, 0);
}

// round 17
// speedup vs baseline: 1.1031x; 1.0082x over previous
#include <cuda_runtime.h>
#include <cuda_fp16.h>
#include <cstdint>
#include <math.h>

// Problem constants
#define D_MODEL 1024
#define NHEADS  16
#define DK      64
#define BATCH   2048
#define SEQ     20
#define M_TOTAL (BATCH * SEQ)   // 40960

#define NCHUNK 5

// ---------------------------------------------------------------------------
// Scratch (fp16)
// ---------------------------------------------------------------------------
__device__ __half g_xh[(size_t)M_TOTAL * D_MODEL];
__device__ __half g_wh[3][(size_t)D_MODEL * D_MODEL];
__device__ __half g_qh[(size_t)M_TOTAL * D_MODEL];
__device__ __half g_kh[(size_t)M_TOTAL * D_MODEL];
__device__ __half g_vh[(size_t)M_TOTAL * D_MODEL];

// ---------------------------------------------------------------------------
// Merged fp32 -> fp16 conversion with streaming 16B loads/stores.
// ---------------------------------------------------------------------------
struct alignas(16) Half8 { __half2 a, b, c, d; };

#define XBLKS 10240
#define WBLKS 256

__global__ __launch_bounds__(256) void f2h_multi(
    const float* __restrict__ X,
    const float* __restrict__ Wq, const float* __restrict__ Wk, const float* __restrict__ Wv)
{
    const float* src;
    __half* dst;
    int local;
    if (blockIdx.x < XBLKS) {
        src = X; dst = g_xh; local = blockIdx.x;
    } else {
        int w = (blockIdx.x - XBLKS) / WBLKS;
        local = (blockIdx.x - XBLKS) % WBLKS;
        src = (w == 0) ? Wq : (w == 1) ? Wk : Wv;
        dst = &g_wh[w][0];
    }
    int c0 = (local * 256 + threadIdx.x) * 2;    // exact fit
    float4 v[4];
    #pragma unroll
    for (int u = 0; u < 4; u++)
        v[u] = __ldcs(&((const float4*)src)[c0 * 2 + u]);
    #pragma unroll
    for (int u = 0; u < 2; u++) {
        Half8 h;
        h.a = __floats2half2_rn(v[2 * u].x,     v[2 * u].y);
        h.b = __floats2half2_rn(v[2 * u].z,     v[2 * u].w);
        h.c = __floats2half2_rn(v[2 * u + 1].x, v[2 * u + 1].y);
        h.d = __floats2half2_rn(v[2 * u + 1].z, v[2 * u + 1].w);
        __stcs((float4*)&((Half8*)dst)[c0 + u], *(float4*)&h);
    }
}

// ---------------------------------------------------------------------------
// MMA / ldmatrix helpers
// ---------------------------------------------------------------------------
__device__ __forceinline__ void mma16(float* c, const uint32_t* a, const uint32_t* b) {
    asm volatile(
        "mma.sync.aligned.m16n8k16.row.col.f32.f16.f16.f32 "
        "{%0,%1,%2,%3}, {%4,%5,%6,%7}, {%8,%9}, {%0,%1,%2,%3};"
        : "+f"(c[0]), "+f"(c[1]), "+f"(c[2]), "+f"(c[3])
        : "r"(a[0]), "r"(a[1]), "r"(a[2]), "r"(a[3]),
          "r"(b[0]), "r"(b[1]));
}
__device__ __forceinline__ void ldmatrix_x4(uint32_t* r, uint32_t addr) {
    asm volatile("ldmatrix.sync.aligned.m8n8.x4.shared.b16 {%0,%1,%2,%3}, [%4];"
                 : "=r"(r[0]), "=r"(r[1]), "=r"(r[2]), "=r"(r[3]) : "r"(addr));
}
__device__ __forceinline__ void ldmatrix_x2(uint32_t* r, uint32_t addr) {
    asm volatile("ldmatrix.sync.aligned.m8n8.x2.shared.b16 {%0,%1}, [%2];"
                 : "=r"(r[0]), "=r"(r[1]) : "r"(addr));
}
__device__ __forceinline__ void cp16(uint32_t saddr, const void* g) {
    asm volatile("cp.async.cg.shared.global [%0], [%1], 16;\n" :: "r"(saddr), "l"(g));
}
#define CP_COMMIT() asm volatile("cp.async.commit_group;\n" ::: "memory")
#define CP_WAIT(n)  asm volatile("cp.async.wait_group %0;\n" :: "n"(n) : "memory")

__device__ __forceinline__ uint32_t smem_u32(const void* p) {
    uint32_t a;
    asm("{ .reg .u64 t; cvta.to.shared.u64 t, %1; cvt.u32.u64 %0, t; }"
        : "=r"(a) : "l"(p));
    return a;
}

// ---------------------------------------------------------------------------
// Projection GEMM: Y = X @ W^T + b, chunked over M. 2 CTAs/SM.
// BM=128, BN=128, BK=32, NSTAGE=4 cp.async with CP_WAIT(1): at the barrier of
// iter kt, stages kt AND kt+1 are fully visible.
// Fragment software pipeline (static buffers, no swap):
//   iter kt: ld frags[1]<-(kt,ks1); MMA frags[0]; ld frags[0]<-(kt+1,ks0);
//            MMA frags[1]; wait+barrier; commit load_stage(kt+3).
// B-fragments packed 2 nt-tiles per ldmatrix.x4.
// ---------------------------------------------------------------------------
#define GM_BM 128
#define GM_BN 128
#define GM_BK 32
#define WSTRIDE 20                         // words per row (= 40 halves)
#define A_STG_WORDS (GM_BM * WSTRIDE)     // 2560
#define B_STG_WORDS (GM_BN * WSTRIDE)     // 2560
#define STG_WORDS   (A_STG_WORDS + B_STG_WORDS)  // 5120
#define NSTAGE 4
#define GM_SMEM_BYTES (NSTAGE * STG_WORDS * 4)   // 81920
#define GM_KT (D_MODEL / GM_BK)           // 32

__global__ __launch_bounds__(256, 2) void proj_gemm(
    const float* __restrict__ bq, const float* __restrict__ bk, const float* __restrict__ bv,
    int mtOff)
{
    extern __shared__ uint32_t smem[];
    const uint32_t sb = smem_u32(smem);

    const int tid  = threadIdx.x;
    const int lane = tid & 31;
    const int warp = tid >> 5;
    const int wr   = warp >> 2;
    const int wc   = warp & 3;
    const int g    = lane >> 2;
    const int tq   = lane & 3;

    const int proj  = blockIdx.x >> 3;
    const int nBase = (blockIdx.x & 7) * GM_BN;
    const int mBase = (mtOff + blockIdx.y) * GM_BM;

    const __half* Wp = g_wh[proj];

    auto load_stage = [&](int stg, int kt) {
        uint32_t base = sb + stg * (STG_WORDS * 4);
        int k0 = kt * GM_BK;
        #pragma unroll
        for (int i = 0; i < 2; i++) {
            int ch = tid + i * 256;
            int r = ch >> 2, c = ch & 3;
            cp16(base + (r * WSTRIDE + c * 4) * 4,
                 &g_xh[(size_t)(mBase + r) * D_MODEL + k0 + c * 8]);
        }
        #pragma unroll
        for (int i = 0; i < 2; i++) {
            int ch = tid + i * 256;
            int r = ch >> 2, c = ch & 3;
            cp16(base + (A_STG_WORDS + r * WSTRIDE + c * 4) * 4,
                 &Wp[(size_t)(nBase + r) * D_MODEL + k0 + c * 8]);
        }
        CP_COMMIT();
    };

    float c[4][4][4];
    #pragma unroll
    for (int mt = 0; mt < 4; mt++)
        #pragma unroll
        for (int nt = 0; nt < 4; nt++)
            #pragma unroll
            for (int i = 0; i < 4; i++) c[mt][nt][i] = 0.f;

    // ldmatrix lane mapping (identical for A x4 and packed-B x4)
    const int fRow = (lane & 15);
    const int fCol = (lane >> 4) * 8;

    uint32_t af[2][4][4];    // [buf][mt][frag]
    uint32_t bf[2][4][2];    // [buf][nt][frag]

    // Load frag set (buf) from stage base for k-half ks
    auto load_frags = [&](int buf, uint32_t sA, int ks) {
        const uint32_t sB = sA + A_STG_WORDS * 4;
        #pragma unroll
        for (int mt = 0; mt < 4; mt++) {
            int row = wr * 64 + mt * 16 + fRow;
            ldmatrix_x4(af[buf][mt], sA + (row * 40 + ks * 16 + fCol) * 2);
        }
        #pragma unroll
        for (int p = 0; p < 2; p++) {
            uint32_t t[4];
            int row = wc * 32 + p * 16 + fRow;
            ldmatrix_x4(t, sB + (row * 40 + ks * 16 + fCol) * 2);
            bf[buf][2 * p][0]     = t[0];
            bf[buf][2 * p + 1][0] = t[1];
            bf[buf][2 * p][1]     = t[2];
            bf[buf][2 * p + 1][1] = t[3];
        }
    };

    auto mma_all = [&](int buf) {
        #pragma unroll
        for (int mt = 0; mt < 4; mt++)
            #pragma unroll
            for (int nt = 0; nt < 4; nt++)
                mma16(c[mt][nt], af[buf][mt], bf[buf][nt]);
    };

    load_stage(0, 0);
    load_stage(1, 1);
    load_stage(2, 2);
    CP_WAIT(1);            // stages 0,1 complete
    __syncthreads();       // visible to all threads
    load_frags(0, sb, 0);  // (kt=0, ks=0)

    for (int kt = 0; kt < GM_KT; kt++) {
        uint32_t sCur = sb + (kt & 3) * (STG_WORDS * 4);
        uint32_t sNxt = sb + ((kt + 1) & 3) * (STG_WORDS * 4);

        if (kt + 3 < GM_KT) load_stage((kt + 3) & 3, kt + 3);

        load_frags(1, sCur, 1);            // (kt, ks1)
        mma_all(0);                        // (kt, ks0)
        if (kt + 1 < GM_KT)
            load_frags(0, sNxt, 0);        // (kt+1, ks0) — stage visible
        mma_all(1);                        // (kt, ks1)

        if (kt + 3 < GM_KT) CP_WAIT(1);
        else                CP_WAIT(0);
        __syncthreads();
    }

    const float* bp = (proj == 0) ? bq : (proj == 1) ? bk : bv;
    __half* outp    = (proj == 0) ? g_qh : (proj == 1) ? g_kh : g_vh;
    #pragma unroll
    for (int mt = 0; mt < 4; mt++) {
        #pragma unroll
        for (int nt = 0; nt < 4; nt++) {
            int row = mBase + wr * 64 + mt * 16 + g;
            int col = nBase + wc * 32 + nt * 8 + 2 * tq;
            float b0 = bp[col], b1 = bp[col + 1];
            __half2 h01 = __floats2half2_rn(c[mt][nt][0] + b0, c[mt][nt][1] + b1);
            __half2 h23 = __floats2half2_rn(c[mt][nt][2] + b0, c[mt][nt][3] + b1);
            *(__half2*)&outp[(size_t)row * D_MODEL + col] = h01;
            *(__half2*)&outp[(size_t)(row + 8) * D_MODEL + col] = h23;
        }
    }
}

// ---------------------------------------------------------------------------
// Attention + decay (R9/R12-validated), chunked over (b,h).
// ---------------------------------------------------------------------------
#define QK_STRIDE 72   // halves per row; 144 B = 9 x 16 B (ldmatrix-aligned)

__global__ __launch_bounds__(128) void attn_kernel(
    const int* __restrict__ lenbuf, float* __restrict__ out, int bhOff)
{
    const int bh = bhOff + blockIdx.x;
    const int b  = bh >> 4;
    const int h  = bh & 15;
    const int tid  = threadIdx.x;
    const int warp = tid >> 5;
    const int lane = tid & 31;

    __shared__ __align__(16) __half sqh[32][QK_STRIDE];
    __shared__ __align__(16) __half skh[24][QK_STRIDE];
    __shared__ __align__(16) float sv[SEQ][68];
    __shared__ float ssc[SEQ][24];
    __shared__ float sinv[SEQ];
    __shared__ __align__(16) float wgtT[SEQ][24];   // [j][i]

    for (int i = tid; i < 32 * (QK_STRIDE / 2); i += 128) ((uint32_t*)sqh)[i] = 0;
    for (int i = tid; i < 24 * (QK_STRIDE / 2); i += 128) ((uint32_t*)skh)[i] = 0;
    __syncthreads();

    {
        size_t base = (size_t)(b * SEQ) * D_MODEL + h * DK;
        for (int e = tid; e < SEQ * (DK / 8); e += 128) {
            int s = e >> 3, d8 = (e & 7) * 8;
            size_t gi = base + (size_t)s * D_MODEL + d8;
            Half8 q8 = *(const Half8*)&g_qh[gi];
            Half8 k8 = *(const Half8*)&g_kh[gi];
            Half8 v8 = *(const Half8*)&g_vh[gi];
            *(Half8*)&sqh[s][d8] = q8;
            *(Half8*)&skh[s][d8] = k8;
            float2 fa = __half22float2(v8.a), fb = __half22float2(v8.b);
            float2 fc = __half22float2(v8.c), fd = __half22float2(v8.d);
            *(float4*)&sv[s][d8]     = make_float4(fa.x, fa.y, fb.x, fb.y);
            *(float4*)&sv[s][d8 + 4] = make_float4(fc.x, fc.y, fd.x, fd.y);
        }
    }
    __syncthreads();

    // length may be int64 or int32 (jax x64 config). All lengths >= 1,
    // so int32-view word 1 == 0 iff buffer is int64.
    bool is64 = (lenbuf[1] == 0);
    int len = is64 ? lenbuf[2 * b] : lenbuf[b];

    if (warp < 3) {
        float c[2][4];
        #pragma unroll
        for (int mt = 0; mt < 2; mt++)
            #pragma unroll
            for (int i = 0; i < 4; i++) c[mt][i] = 0.f;

        const uint32_t sq_base = smem_u32(&sqh[0][0]);
        const uint32_t sk_base = smem_u32(&skh[0][0]);

        #pragma unroll
        for (int ks = 0; ks < 4; ks++) {
            uint32_t bfrag[2];
            {
                int l = lane & 15;
                int row = warp * 8 + (l & 7);
                int col = ks * 16 + ((l >> 3) & 1) * 8;
                ldmatrix_x2(bfrag, sk_base + (row * QK_STRIDE + col) * 2);
            }
            #pragma unroll
            for (int mt = 0; mt < 2; mt++) {
                uint32_t afrag[4];
                int row = mt * 16 + (lane & 15);
                int col = ks * 16 + (lane >> 4) * 8;
                ldmatrix_x4(afrag, sq_base + (row * QK_STRIDE + col) * 2);
                mma16(c[mt], afrag, bfrag);
            }
        }

        int jc = warp * 8 + 2 * (lane & 3);
        bool jv0 = (jc < SEQ), jv1 = (jc + 1 < SEQ);
        float m0 = (jc < len) ? 1.f : 0.f;
        float m1 = (jc + 1 < len) ? 1.f : 0.f;
        #pragma unroll
        for (int mt = 0; mt < 2; mt++) {
            #pragma unroll
            for (int hrow = 0; hrow < 2; hrow++) {
                int r = mt * 16 + (lane >> 2) + hrow * 8;
                if (r < SEQ) {
                    if (jv0) ssc[r][jc]     = m0 * __expf(c[mt][2 * hrow]     * 0.125f);
                    if (jv1) ssc[r][jc + 1] = m1 * __expf(c[mt][2 * hrow + 1] * 0.125f);
                }
            }
        }
    }
    __syncthreads();

    if (tid < SEQ) {
        float s = 0.f;
        #pragma unroll
        for (int j = 0; j < SEQ; j++) s += ssc[tid][j];
        sinv[tid] = 1.f / (s + 1e-8f);
    }
    __syncthreads();

    for (int e = tid; e < SEQ * SEQ; e += 128) {
        int i = e % SEQ, j = e / SEQ;
        wgtT[j][i] = ssc[i][j] * sinv[i] - (float)((i > j) ? (i - j) : (j - i));
    }
    __syncthreads();

    if (tid < 80) {
        int i0 = (tid / 16) * 4;
        int d0 = (tid & 15) * 4;
        float4 o0 = {0, 0, 0, 0}, o1 = {0, 0, 0, 0}, o2 = {0, 0, 0, 0}, o3 = {0, 0, 0, 0};
        #pragma unroll
        for (int j = 0; j < SEQ; j++) {
            float4 vv = *(const float4*)&sv[j][d0];
            float4 w  = *(const float4*)&wgtT[j][i0];
            o0.x += w.x * vv.x; o0.y += w.x * vv.y; o0.z += w.x * vv.z; o0.w += w.x * vv.w;
            o1.x += w.y * vv.x; o1.y += w.y * vv.y; o1.z += w.y * vv.z; o1.w += w.y * vv.w;
            o2.x += w.z * vv.x; o2.y += w.z * vv.y; o2.z += w.z * vv.z; o2.w += w.z * vv.w;
            o3.x += w.w * vv.x; o3.y += w.w * vv.y; o3.z += w.w * vv.z; o3.w += w.w * vv.w;
        }
        size_t base = (size_t)(b * SEQ + i0) * D_MODEL + h * DK + d0;
        __stcs((float4*)&out[base],               o0);
        __stcs((float4*)&out[base + D_MODEL],     o1);
        __stcs((float4*)&out[base + 2 * D_MODEL], o2);
        __stcs((float4*)&out[base + 3 * D_MODEL], o3);
    }
}

// ---------------------------------------------------------------------------
// Inputs (metadata order): Q, W_Q, b_Q, W_K, b_K, W_V, b_V, length
// Wave-exact fork-join overlap (R16): GEMM chunks {74,74,74,74,24} m-tiles,
// attn chunks follow covered-sequence boundaries.
// ---------------------------------------------------------------------------
extern "C" void kernel_launch(void* const* d_in, const int* in_sizes, int n_in,
                              void* d_out, int out_size)
{
    const float* X  = (const float*)d_in[0];
    const float* Wq = (const float*)d_in[1];
    const float* bq = (const float*)d_in[2];
    const float* Wk = (const float*)d_in[3];
    const float* bk = (const float*)d_in[4];
    const float* Wv = (const float*)d_in[5];
    const float* bv = (const float*)d_in[6];
    const int*   ln = (const int*)d_in[7];

    static const int mtSize[NCHUNK] = {74, 74, 74, 74, 24};
    static const int mtOff[NCHUNK]  = {0, 74, 148, 222, 296};
    static const int bEnd[NCHUNK]   = {473, 947, 1420, 1894, 2048};

    static cudaStream_t s2 = nullptr;
    static cudaEvent_t evc[NCHUNK], evj;
    if (!s2) {
        cudaStreamCreateWithFlags(&s2, cudaStreamNonBlocking);
        for (int c = 0; c < NCHUNK; c++)
            cudaEventCreateWithFlags(&evc[c], cudaEventDisableTiming);
        cudaEventCreateWithFlags(&evj, cudaEventDisableTiming);
    }

    f2h_multi<<<XBLKS + 3 * WBLKS, 256>>>(X, Wq, Wk, Wv);

    cudaFuncSetAttribute(proj_gemm,
                         cudaFuncAttributeMaxDynamicSharedMemorySize, GM_SMEM_BYTES);

    for (int c = 0; c < NCHUNK; c++) {
        dim3 ggrid(3 * (D_MODEL / GM_BN), mtSize[c]);
        proj_gemm<<<ggrid, 256, GM_SMEM_BYTES>>>(bq, bk, bv, mtOff[c]);
        cudaEventRecord(evc[c], 0);
    }
    int bStart = 0;
    for (int c = 0; c < NCHUNK; c++) {
        cudaStreamWaitEvent(s2, evc[c], 0);
        int nbh = (bEnd[c] - bStart) * NHEADS;
        attn_kernel<<<nbh, 128, 0, s2>>>(ln, (float*)d_out, bStart * NHEADS);
        bStart = bEnd[c];
    }
    cudaEventRecord(evj, s2);
    cudaStreamWaitEvent(0, evj, 0);
}